// round 8
// baseline (speedup 1.0000x reference)
#include <cuda_runtime.h>
#include <cuda_fp16.h>
#include <cuda_bf16.h>
#include <mma.h>
#include <stdint.h>

using namespace nvcuda;

#define T_ROWS   256
#define K_DIM    8192
#define M_DIM    8192
#define N_CODES  1024
#define GP_ELEMS 1816   // 227 * 8

// scratch (device globals: allocation-free per harness rules)
__device__ __half  g_gp[2048];               // canonical fp16 codebook
__device__ __half  g_xh[T_ROWS * K_DIM];     // 4 MB
__device__ float   g_z [T_ROWS * M_DIM];     // 8 MB

__device__ __forceinline__ uint32_t smem_u32(const void* p) {
    uint32_t a;
    asm("{ .reg .u64 t; cvta.to.shared.u64 t, %1; cvt.u32.u64 %0, t; }"
        : "=r"(a) : "l"(p));
    return a;
}
__device__ __forceinline__ void cp_async16(uint32_t dst, const void* src) {
    asm volatile("cp.async.cg.shared.global [%0], [%1], 16;" :: "r"(dst), "l"(src));
}

// ---------------------------------------------------------------------------
// K0: normalize grid_part to fp16 regardless of delivered dtype.
// ---------------------------------------------------------------------------
__global__ void prep_gp_kernel(const void* __restrict__ gp_raw)
{
    const uint32_t w0 = *(const uint32_t*)gp_raw;
    const int i = threadIdx.x + blockIdx.x * blockDim.x;
    if (i >= GP_ELEMS) return;
    float v;
    if (w0 == 0x3F000000u)        v = ((const float*)gp_raw)[i];
    else if (w0 == 0x3F003F00u)   v = __bfloat162float(((const __nv_bfloat16*)gp_raw)[i]);
    else                          v = __half2float(((const __half*)gp_raw)[i]);
    g_gp[i] = __float2half(v);
}

// ---------------------------------------------------------------------------
// K1: x = SU*x ; FWHT(8192) ; /(sqrt(8192)*1024) ; fp16   (256 threads)
// ---------------------------------------------------------------------------
__global__ void fwht_in_kernel(const float* __restrict__ x,
                               const float* __restrict__ SU)
{
    __shared__ float s[K_DIM];
    const int row = blockIdx.x;
    const float* xr = x + (size_t)row * K_DIM;
    for (int i = threadIdx.x; i < K_DIM; i += 256)
        s[i] = xr[i] * SU[i];
    __syncthreads();
    for (int h = 1; h < K_DIM; h <<= 1) {
        #pragma unroll 1
        for (int j = 0; j < 16; j++) {
            int i   = threadIdx.x + j * 256;
            int idx = ((i & ~(h - 1)) << 1) | (i & (h - 1));
            float a = s[idx], b = s[idx + h];
            s[idx]     = a + b;
            s[idx + h] = a - b;
        }
        __syncthreads();
    }
    const float c = 1.0789593218788508e-05f;   // 1/(sqrt(8192)*1024)
    __half* o = g_xh + (size_t)row * K_DIM;
    for (int i = threadIdx.x; i < K_DIM; i += 256)
        o[i] = __float2half(s[i] * c);
}

// ---------------------------------------------------------------------------
// K3: fused dequant + wmma GEMM
// block 128(m) x 128(n), 4 warps (2x2), warp tile 64x64 (acc 4x4).
// K-chunk 64, 3-stage cp.async pipeline, LUT decode (1 row/thread).
// ---------------------------------------------------------------------------
#define STAGES      3
#define NCHUNK      128            // 8192 / 64
#define BMT         128
#define BNT         128
#define LDSM        72             // 64 + 8 pad halves; 144B row stride
#define A_BYTES     (128 * 144)    // 18432
#define B_BYTES     (128 * 144)    // 18432
#define STAGE_BYTES (A_BYTES + B_BYTES)
#define SM_CB       0              // codebook 227*16B
#define SM_LUT      3712           // sign LUT 256*16B
#define SM_STAGE    7808
#define SMEM_GEMM   (SM_STAGE + STAGES * STAGE_BYTES)   // 118400

__global__ void __launch_bounds__(128) gemm_fused_kernel(const int* __restrict__ Q)
{
    extern __shared__ char smem[];
    const uint32_t sb = smem_u32(smem);
    const int tid = threadIdx.x;
    const int warpId = tid >> 5;          // 0..3
    const int warpM  = warpId >> 1;       // 0..1 -> 64 m-rows
    const int warpN  = warpId & 1;        // 0..1 -> 64 n-cols
    const int n0 = blockIdx.x * BNT;
    const int m0 = blockIdx.y * BMT;

    if (tid < 114) {   // codebook (227 rows, 2 per thread)
        *(uint4*)(smem + SM_CB + tid * 32) = *(const uint4*)(g_gp + tid * 16);
        if (tid * 2 + 1 < 227)
            *(uint4*)(smem + SM_CB + tid * 32 + 16) = *(const uint4*)(g_gp + tid * 16 + 8);
    }
    {   // sign LUT, 2 entries per thread
        #pragma unroll
        for (int u = 0; u < 2; u++) {
            uint32_t f = tid + u * 128;
            uint4 m;
            m.x = ((f & 1)  ? 0x8000u : 0u) | ((f & 2)   ? 0x80000000u : 0u);
            m.y = ((f & 4)  ? 0x8000u : 0u) | ((f & 8)   ? 0x80000000u : 0u);
            m.z = ((f & 16) ? 0x8000u : 0u) | ((f & 32)  ? 0x80000000u : 0u);
            m.w = ((f & 64) ? 0x8000u : 0u) | ((f & 128) ? 0x80000000u : 0u);
            *(uint4*)(smem + SM_LUT + f * 16) = m;
        }
    }
    __syncthreads();

    // B decode: thread t owns B-row t; chunk c needs codes [c*8, c*8+8) = 2 int4
    const int4* qrow = (const int4*)(Q + (size_t)(n0 + tid) * N_CODES);

    wmma::fragment<wmma::accumulator, 16, 16, 16, float> acc[4][4];
    #pragma unroll
    for (int i = 0; i < 4; i++)
        #pragma unroll
        for (int j = 0; j < 4; j++)
            wmma::fill_fragment(acc[i][j], 0.0f);

    auto fill = [&](int c, int4 qa, int4 qb) {
        const int s = c % STAGES;
        const uint32_t abase = sb + SM_STAGE + s * STAGE_BYTES;
        // A tile: 128 rows x 128B = 1024 x 16B, 8 per thread
        #pragma unroll
        for (int u = 0; u < 8; u++) {
            int lin = tid + u * 128;
            int row = lin >> 3, c16 = lin & 7;
            cp_async16(abase + row * 144 + c16 * 16,
                       g_xh + (size_t)(m0 + row) * K_DIM + c * 64 + c16 * 8);
        }
        // B tile: decode 8 codes for row `tid`
        char* bb = smem + SM_STAGE + s * STAGE_BYTES + A_BYTES;
        const int qs[8] = {qa.x, qa.y, qa.z, qa.w, qb.x, qb.y, qb.z, qb.w};
        #pragma unroll
        for (int e = 0; e < 8; e++) {
            int idx = qs[e] + 32768;
            const uint4 cb = *(const uint4*)(smem + SM_CB  + (idx & 255) * 16);
            const uint4 sm = *(const uint4*)(smem + SM_LUT + (idx >> 8)  * 16);
            uint4 o;
            o.x = cb.x ^ sm.x;  o.y = cb.y ^ sm.y;
            o.z = cb.z ^ sm.z;  o.w = cb.w ^ sm.w;
            *(uint4*)(bb + tid * 144 + e * 16) = o;
        }
    };

    fill(0, qrow[0], qrow[1]);
    asm volatile("cp.async.commit_group;" ::: "memory");
    fill(1, qrow[2], qrow[3]);
    asm volatile("cp.async.commit_group;" ::: "memory");

    for (int i = 0; i < NCHUNK; i++) {
        int4 qa = {0,0,0,0}, qb = {0,0,0,0};
        if (i + 2 < NCHUNK) { qa = qrow[(i + 2) * 2]; qb = qrow[(i + 2) * 2 + 1]; }

        asm volatile("cp.async.wait_group 1;" ::: "memory");
        __syncthreads();

        const int s = i % STAGES;
        const __half* As = (const __half*)(smem + SM_STAGE + s * STAGE_BYTES);
        const __half* Bs = (const __half*)(smem + SM_STAGE + s * STAGE_BYTES + A_BYTES);
        #pragma unroll
        for (int kk = 0; kk < 4; kk++) {
            wmma::fragment<wmma::matrix_a, 16, 16, 16, __half, wmma::row_major> a[4];
            wmma::fragment<wmma::matrix_b, 16, 16, 16, __half, wmma::col_major> b[4];
            #pragma unroll
            for (int ii = 0; ii < 4; ii++)
                wmma::load_matrix_sync(a[ii], &As[(warpM * 64 + ii * 16) * LDSM + kk * 16], LDSM);
            #pragma unroll
            for (int jj = 0; jj < 4; jj++)
                wmma::load_matrix_sync(b[jj], &Bs[(warpN * 64 + jj * 16) * LDSM + kk * 16], LDSM);
            #pragma unroll
            for (int ii = 0; ii < 4; ii++)
                #pragma unroll
                for (int jj = 0; jj < 4; jj++)
                    wmma::mma_sync(acc[ii][jj], a[ii], b[jj], acc[ii][jj]);
        }
        __syncthreads();

        if (i + 2 < NCHUNK) fill(i + 2, qa, qb);
        asm volatile("cp.async.commit_group;" ::: "memory");
    }

    #pragma unroll
    for (int ii = 0; ii < 4; ii++)
        #pragma unroll
        for (int jj = 0; jj < 4; jj++)
            wmma::store_matrix_sync(
                &g_z[(size_t)(m0 + warpM * 64 + ii * 16) * M_DIM +
                     n0 + warpN * 64 + jj * 16],
                acc[ii][jj], M_DIM, wmma::mem_row_major);
}

// ---------------------------------------------------------------------------
// K4: out = SV * fwht(z) * (Wscale*1024/sqrt(8192))   (256 threads)
// ---------------------------------------------------------------------------
__global__ void fwht_out_kernel(const float* __restrict__ SV,
                                const float* __restrict__ Wscale,
                                float* __restrict__ out)
{
    __shared__ float s[M_DIM];
    const int row = blockIdx.x;
    const float* zr = g_z + (size_t)row * M_DIM;
    for (int i = threadIdx.x; i < M_DIM; i += 256)
        s[i] = zr[i];
    __syncthreads();
    for (int h = 1; h < M_DIM; h <<= 1) {
        #pragma unroll 1
        for (int j = 0; j < 16; j++) {
            int i   = threadIdx.x + j * 256;
            int idx = ((i & ~(h - 1)) << 1) | (i & (h - 1));
            float a = s[idx], b = s[idx + h];
            s[idx]     = a + b;
            s[idx + h] = a - b;
        }
        __syncthreads();
    }
    const float c = Wscale[0] * 11.313708498984761f;  // 1024/sqrt(8192)
    float* o = out + (size_t)row * M_DIM;
    for (int i = threadIdx.x; i < M_DIM; i += 256)
        o[i] = s[i] * c * SV[i];
}

// ---------------------------------------------------------------------------
extern "C" void kernel_launch(void* const* d_in, const int* in_sizes, int n_in,
                              void* d_out, int out_size)
{
    const float* x  = nullptr;  const int*   Q  = nullptr;
    const float* SU = nullptr;  const float* SV = nullptr;
    const float* Ws = nullptr;  const void*  gp = nullptr;
    for (int i = 0; i < n_in; i++) {
        int s = in_sizes[i];
        if      (s == T_ROWS * K_DIM)   x  = (const float*)d_in[i];
        else if (s == M_DIM * N_CODES)  Q  = (const int*)d_in[i];
        else if (s == 1)                Ws = (const float*)d_in[i];
        else if (s == K_DIM) { if (!SU) SU = (const float*)d_in[i];
                               else     SV = (const float*)d_in[i]; }
        else                            gp = d_in[i];
    }
    float* out = (float*)d_out;

    static bool smem_set = false;
    if (!smem_set) {
        cudaFuncSetAttribute(gemm_fused_kernel,
                             cudaFuncAttributeMaxDynamicSharedMemorySize, SMEM_GEMM);
        smem_set = true;
    }

    prep_gp_kernel<<<8, 256>>>(gp);
    fwht_in_kernel<<<T_ROWS, 256>>>(x, SU);
    dim3 grid(M_DIM / BNT, T_ROWS / BMT);
    gemm_fused_kernel<<<grid, 128, SMEM_GEMM>>>(Q);
    fwht_out_kernel<<<T_ROWS, 256>>>(SV, Ws, out);
}

// round 10
// speedup vs baseline: 1.2821x; 1.2821x over previous
#include <cuda_runtime.h>
#include <cuda_fp16.h>
#include <cuda_bf16.h>
#include <mma.h>
#include <stdint.h>

using namespace nvcuda;

#define T_ROWS   256
#define K_DIM    8192
#define M_DIM    8192
#define N_CODES  1024
#define GP_ELEMS 1816   // 227 * 8

// scratch (device globals: allocation-free per harness rules)
__device__ __half  g_gp[2048];               // canonical fp16 codebook
__device__ __half  g_xh[T_ROWS * K_DIM];     // 4 MB
__device__ float   g_z [T_ROWS * M_DIM];     // 8 MB (K-split 0)
__device__ float   g_z2[T_ROWS * M_DIM];     // 8 MB (K-split 1)

__device__ __forceinline__ uint32_t smem_u32(const void* p) {
    uint32_t a;
    asm("{ .reg .u64 t; cvta.to.shared.u64 t, %1; cvt.u32.u64 %0, t; }"
        : "=r"(a) : "l"(p));
    return a;
}
__device__ __forceinline__ void cp_async16(uint32_t dst, const void* src) {
    asm volatile("cp.async.cg.shared.global [%0], [%1], 16;" :: "r"(dst), "l"(src));
}

// ---------------------------------------------------------------------------
// K0: normalize grid_part to fp16 regardless of delivered dtype.
// ---------------------------------------------------------------------------
__global__ void prep_gp_kernel(const void* __restrict__ gp_raw)
{
    const uint32_t w0 = *(const uint32_t*)gp_raw;
    const int i = threadIdx.x + blockIdx.x * blockDim.x;
    if (i >= GP_ELEMS) return;
    float v;
    if (w0 == 0x3F000000u)        v = ((const float*)gp_raw)[i];
    else if (w0 == 0x3F003F00u)   v = __bfloat162float(((const __nv_bfloat16*)gp_raw)[i]);
    else                          v = __half2float(((const __half*)gp_raw)[i]);
    g_gp[i] = __float2half(v);
}

// ---------------------------------------------------------------------------
// K1: x = SU*x ; FWHT(8192) ; /(sqrt(8192)*1024) ; fp16
// ---------------------------------------------------------------------------
__global__ void fwht_in_kernel(const float* __restrict__ x,
                               const float* __restrict__ SU)
{
    __shared__ float s[K_DIM];
    const int row = blockIdx.x;
    const float* xr = x + (size_t)row * K_DIM;
    for (int i = threadIdx.x; i < K_DIM; i += 256)
        s[i] = xr[i] * SU[i];
    __syncthreads();
    for (int h = 1; h < K_DIM; h <<= 1) {
        #pragma unroll 1
        for (int j = 0; j < 16; j++) {
            int i   = threadIdx.x + j * 256;
            int idx = ((i & ~(h - 1)) << 1) | (i & (h - 1));
            float a = s[idx], b = s[idx + h];
            s[idx]     = a + b;
            s[idx + h] = a - b;
        }
        __syncthreads();
    }
    const float c = 1.0789593218788508e-05f;   // 1/(sqrt(8192)*1024)
    __half* o = g_xh + (size_t)row * K_DIM;
    for (int i = threadIdx.x; i < K_DIM; i += 256)
        o[i] = __float2half(s[i] * c);
}

// ---------------------------------------------------------------------------
// K3: fused dequant + wmma GEMM, K-split x2
// block 128(m) x 128(n) x K-half(4096); 4 warps (2x2), warp tile 64x64.
// K-chunk 64, 2-stage cp.async double buffer, LUT decode (1 row/thread).
// grid (64, 2, 2) = 256 blocks -> 2 blocks/SM.
// ---------------------------------------------------------------------------
#define NCHUNK_S    64             // 4096 / 64 per K-split
#define BMT         128
#define BNT         128
#define LDSM        72             // 64 + 8 pad halves; 144B row stride
#define A_BYTES     (128 * 144)    // 18432
#define B_BYTES     (128 * 144)    // 18432
#define STAGE_BYTES (A_BYTES + B_BYTES)
#define SM_CB       0              // codebook 227*16B
#define SM_LUT      3712           // sign LUT 256*16B
#define SM_STAGE    7808
#define SMEM_GEMM   (SM_STAGE + 2 * STAGE_BYTES)   // 81536 -> 2 blocks/SM

__global__ void __launch_bounds__(128, 2) gemm_fused_kernel(const int* __restrict__ Q)
{
    extern __shared__ char smem[];
    const uint32_t sb = smem_u32(smem);
    const int tid = threadIdx.x;
    const int warpId = tid >> 5;          // 0..3
    const int warpM  = warpId >> 1;       // 0..1 -> 64 m-rows
    const int warpN  = warpId & 1;        // 0..1 -> 64 n-cols
    const int n0 = blockIdx.x * BNT;
    const int m0 = blockIdx.y * BMT;
    const int ks = blockIdx.z;            // K-split 0/1
    const int kbase = ks * (K_DIM / 2);

    if (tid < 114) {   // codebook (227 rows, 2 per thread)
        *(uint4*)(smem + SM_CB + tid * 32) = *(const uint4*)(g_gp + tid * 16);
        if (tid * 2 + 1 < 227)
            *(uint4*)(smem + SM_CB + tid * 32 + 16) = *(const uint4*)(g_gp + tid * 16 + 8);
    }
    {   // sign LUT, 2 entries per thread
        #pragma unroll
        for (int u = 0; u < 2; u++) {
            uint32_t f = tid + u * 128;
            uint4 m;
            m.x = ((f & 1)  ? 0x8000u : 0u) | ((f & 2)   ? 0x80000000u : 0u);
            m.y = ((f & 4)  ? 0x8000u : 0u) | ((f & 8)   ? 0x80000000u : 0u);
            m.z = ((f & 16) ? 0x8000u : 0u) | ((f & 32)  ? 0x80000000u : 0u);
            m.w = ((f & 64) ? 0x8000u : 0u) | ((f & 128) ? 0x80000000u : 0u);
            *(uint4*)(smem + SM_LUT + f * 16) = m;
        }
    }
    __syncthreads();

    // B decode: thread t owns B-row t; split ks -> code offset ks*512 = 128 int4
    const int4* qrow = (const int4*)(Q + (size_t)(n0 + tid) * N_CODES) + ks * 128;

    wmma::fragment<wmma::accumulator, 16, 16, 16, float> acc[4][4];
    #pragma unroll
    for (int i = 0; i < 4; i++)
        #pragma unroll
        for (int j = 0; j < 4; j++)
            wmma::fill_fragment(acc[i][j], 0.0f);

    auto fill = [&](int c, int4 qa, int4 qb) {
        const int s = c & 1;
        const uint32_t abase = sb + SM_STAGE + s * STAGE_BYTES;
        // A tile: 128 rows x 128B = 1024 x 16B, 8 per thread
        #pragma unroll
        for (int u = 0; u < 8; u++) {
            int lin = tid + u * 128;
            int row = lin >> 3, c16 = lin & 7;
            cp_async16(abase + row * 144 + c16 * 16,
                       g_xh + (size_t)(m0 + row) * K_DIM + kbase + c * 64 + c16 * 8);
        }
        // B tile: decode 8 codes for row `tid`
        char* bb = smem + SM_STAGE + s * STAGE_BYTES + A_BYTES;
        const int qs[8] = {qa.x, qa.y, qa.z, qa.w, qb.x, qb.y, qb.z, qb.w};
        #pragma unroll
        for (int e = 0; e < 8; e++) {
            int idx = qs[e] + 32768;
            const uint4 cb = *(const uint4*)(smem + SM_CB  + (idx & 255) * 16);
            const uint4 sm = *(const uint4*)(smem + SM_LUT + (idx >> 8)  * 16);
            uint4 o;
            o.x = cb.x ^ sm.x;  o.y = cb.y ^ sm.y;
            o.z = cb.z ^ sm.z;  o.w = cb.w ^ sm.w;
            *(uint4*)(bb + tid * 144 + e * 16) = o;
        }
    };

    fill(0, qrow[0], qrow[1]);
    asm volatile("cp.async.commit_group;" ::: "memory");

    for (int i = 0; i < NCHUNK_S; i++) {
        if (i + 1 < NCHUNK_S)
            fill(i + 1, qrow[(i + 1) * 2], qrow[(i + 1) * 2 + 1]);
        asm volatile("cp.async.commit_group;" ::: "memory");
        asm volatile("cp.async.wait_group 1;" ::: "memory");
        __syncthreads();

        const int s = i & 1;
        const __half* As = (const __half*)(smem + SM_STAGE + s * STAGE_BYTES);
        const __half* Bs = (const __half*)(smem + SM_STAGE + s * STAGE_BYTES + A_BYTES);
        #pragma unroll
        for (int kk = 0; kk < 4; kk++) {
            wmma::fragment<wmma::matrix_a, 16, 16, 16, __half, wmma::row_major> a[4];
            wmma::fragment<wmma::matrix_b, 16, 16, 16, __half, wmma::col_major> b[4];
            #pragma unroll
            for (int ii = 0; ii < 4; ii++)
                wmma::load_matrix_sync(a[ii], &As[(warpM * 64 + ii * 16) * LDSM + kk * 16], LDSM);
            #pragma unroll
            for (int jj = 0; jj < 4; jj++)
                wmma::load_matrix_sync(b[jj], &Bs[(warpN * 64 + jj * 16) * LDSM + kk * 16], LDSM);
            #pragma unroll
            for (int ii = 0; ii < 4; ii++)
                #pragma unroll
                for (int jj = 0; jj < 4; jj++)
                    wmma::mma_sync(acc[ii][jj], a[ii], b[jj], acc[ii][jj]);
        }
        __syncthreads();
    }

    float* zbase = ks ? g_z2 : g_z;
    #pragma unroll
    for (int ii = 0; ii < 4; ii++)
        #pragma unroll
        for (int jj = 0; jj < 4; jj++)
            wmma::store_matrix_sync(
                &zbase[(size_t)(m0 + warpM * 64 + ii * 16) * M_DIM +
                       n0 + warpN * 64 + jj * 16],
                acc[ii][jj], M_DIM, wmma::mem_row_major);
}

// ---------------------------------------------------------------------------
// K4: out = SV * fwht(z0 + z1) * (Wscale*1024/sqrt(8192))
// ---------------------------------------------------------------------------
__global__ void fwht_out_kernel(const float* __restrict__ SV,
                                const float* __restrict__ Wscale,
                                float* __restrict__ out)
{
    __shared__ float s[M_DIM];
    const int row = blockIdx.x;
    const float* z0 = g_z  + (size_t)row * M_DIM;
    const float* z1 = g_z2 + (size_t)row * M_DIM;
    for (int i = threadIdx.x; i < M_DIM; i += 256)
        s[i] = z0[i] + z1[i];
    __syncthreads();
    for (int h = 1; h < M_DIM; h <<= 1) {
        #pragma unroll 1
        for (int j = 0; j < 16; j++) {
            int i   = threadIdx.x + j * 256;
            int idx = ((i & ~(h - 1)) << 1) | (i & (h - 1));
            float a = s[idx], b = s[idx + h];
            s[idx]     = a + b;
            s[idx + h] = a - b;
        }
        __syncthreads();
    }
    const float c = Wscale[0] * 11.313708498984761f;  // 1024/sqrt(8192)
    float* o = out + (size_t)row * M_DIM;
    for (int i = threadIdx.x; i < M_DIM; i += 256)
        o[i] = s[i] * c * SV[i];
}

// ---------------------------------------------------------------------------
extern "C" void kernel_launch(void* const* d_in, const int* in_sizes, int n_in,
                              void* d_out, int out_size)
{
    const float* x  = nullptr;  const int*   Q  = nullptr;
    const float* SU = nullptr;  const float* SV = nullptr;
    const float* Ws = nullptr;  const void*  gp = nullptr;
    for (int i = 0; i < n_in; i++) {
        int s = in_sizes[i];
        if      (s == T_ROWS * K_DIM)   x  = (const float*)d_in[i];
        else if (s == M_DIM * N_CODES)  Q  = (const int*)d_in[i];
        else if (s == 1)                Ws = (const float*)d_in[i];
        else if (s == K_DIM) { if (!SU) SU = (const float*)d_in[i];
                               else     SV = (const float*)d_in[i]; }
        else                            gp = d_in[i];
    }
    float* out = (float*)d_out;

    static bool smem_set = false;
    if (!smem_set) {
        cudaFuncSetAttribute(gemm_fused_kernel,
                             cudaFuncAttributeMaxDynamicSharedMemorySize, SMEM_GEMM);
        smem_set = true;
    }

    prep_gp_kernel<<<8, 256>>>(gp);
    fwht_in_kernel<<<T_ROWS, 256>>>(x, SU);
    dim3 grid(M_DIM / BNT, T_ROWS / BMT, 2);
    gemm_fused_kernel<<<grid, 128, SMEM_GEMM>>>(Q);
    fwht_out_kernel<<<T_ROWS, 256>>>(SV, Ws, out);
}

// round 11
// speedup vs baseline: 1.4226x; 1.1095x over previous
#include <cuda_runtime.h>
#include <cuda_fp16.h>
#include <cuda_bf16.h>
#include <mma.h>
#include <stdint.h>

using namespace nvcuda;

#define T_ROWS   256
#define K_DIM    8192
#define M_DIM    8192
#define N_CODES  1024
#define GP_ELEMS 1816   // 227 * 8

// scratch (device globals: allocation-free per harness rules)
__device__ __half  g_gp[2048];               // canonical fp16 codebook
__device__ __half  g_xh[T_ROWS * K_DIM];     // 4 MB
__device__ float   g_z [T_ROWS * M_DIM];     // 8 MB (K-split 0)
__device__ float   g_z2[T_ROWS * M_DIM];     // 8 MB (K-split 1)

__device__ __forceinline__ uint32_t smem_u32(const void* p) {
    uint32_t a;
    asm("{ .reg .u64 t; cvta.to.shared.u64 t, %1; cvt.u32.u64 %0, t; }"
        : "=r"(a) : "l"(p));
    return a;
}
__device__ __forceinline__ void cp_async16(uint32_t dst, const void* src) {
    asm volatile("cp.async.cg.shared.global [%0], [%1], 16;" :: "r"(dst), "l"(src));
}

// ---------------------------------------------------------------------------
// K0: normalize grid_part to fp16 regardless of delivered dtype.
// ---------------------------------------------------------------------------
__global__ void prep_gp_kernel(const void* __restrict__ gp_raw)
{
    const uint32_t w0 = *(const uint32_t*)gp_raw;
    const int i = threadIdx.x + blockIdx.x * blockDim.x;
    if (i >= GP_ELEMS) return;
    float v;
    if (w0 == 0x3F000000u)        v = ((const float*)gp_raw)[i];
    else if (w0 == 0x3F003F00u)   v = __bfloat162float(((const __nv_bfloat16*)gp_raw)[i]);
    else                          v = __half2float(((const __half*)gp_raw)[i]);
    g_gp[i] = __float2half(v);
}

// ---------------------------------------------------------------------------
// Fast FWHT core: 8192 = reg(32) x warp(8) x lane(32) decomposition.
// Thread t holds v[r] = data[r*256 + t]. Stages commute:
//  bits 8..12 -> register FWHT_32 ; bits 0..4 -> shfl_xor ; bits 5..7 -> smem.
// ---------------------------------------------------------------------------
__device__ __forceinline__ void fwht8192_core(float (&v)[32], float* sm, int t)
{
    const int lane = t & 31;
    // register stages (element bits 8..12)
    #pragma unroll
    for (int b = 1; b < 32; b <<= 1)
        #pragma unroll
        for (int r = 0; r < 32; r++)
            if (!(r & b)) {
                float a = v[r], c2 = v[r | b];
                v[r]     = a + c2;
                v[r | b] = a - c2;
            }
    // lane stages (element bits 0..4)
    #pragma unroll
    for (int m = 1; m < 32; m <<= 1)
        #pragma unroll
        for (int r = 0; r < 32; r++) {
            float w = __shfl_xor_sync(0xFFFFFFFFu, v[r], m);
            v[r] = (lane & m) ? (w - v[r]) : (v[r] + w);
        }
    // warp stages (element bits 5..7): 3 smem exchange rounds
    #pragma unroll
    for (int mb = 32; mb < 256; mb <<= 1) {
        #pragma unroll
        for (int r = 0; r < 32; r++) sm[r * 256 + t] = v[r];
        __syncthreads();
        #pragma unroll
        for (int r = 0; r < 32; r++) {
            float w = sm[r * 256 + (t ^ mb)];
            v[r] = (t & mb) ? (w - v[r]) : (v[r] + w);
        }
        __syncthreads();
    }
}

// ---------------------------------------------------------------------------
// K1: x = SU*x ; FWHT(8192) ; /(sqrt(8192)*1024) ; fp16
// ---------------------------------------------------------------------------
__global__ void __launch_bounds__(256) fwht_in_kernel(const float* __restrict__ x,
                                                      const float* __restrict__ SU)
{
    __shared__ float sm[K_DIM];
    const int row = blockIdx.x;
    const int t = threadIdx.x;
    const float* xr = x + (size_t)row * K_DIM;
    float v[32];
    #pragma unroll
    for (int r = 0; r < 32; r++) {
        int i = r * 256 + t;
        v[r] = xr[i] * SU[i];
    }
    fwht8192_core(v, sm, t);
    const float c = 1.0789593218788508e-05f;   // 1/(sqrt(8192)*1024)
    __half* o = g_xh + (size_t)row * K_DIM;
    #pragma unroll
    for (int r = 0; r < 32; r++)
        o[r * 256 + t] = __float2half(v[r] * c);
}

// ---------------------------------------------------------------------------
// K3: fused dequant + wmma GEMM, K-split x2  (UNCHANGED from R10 winner)
// ---------------------------------------------------------------------------
#define NCHUNK_S    64             // 4096 / 64 per K-split
#define BMT         128
#define BNT         128
#define LDSM        72             // 64 + 8 pad halves; 144B row stride
#define A_BYTES     (128 * 144)    // 18432
#define B_BYTES     (128 * 144)    // 18432
#define STAGE_BYTES (A_BYTES + B_BYTES)
#define SM_CB       0              // codebook 227*16B
#define SM_LUT      3712           // sign LUT 256*16B
#define SM_STAGE    7808
#define SMEM_GEMM   (SM_STAGE + 2 * STAGE_BYTES)   // 81536 -> 2 blocks/SM

__global__ void __launch_bounds__(128, 2) gemm_fused_kernel(const int* __restrict__ Q)
{
    extern __shared__ char smem[];
    const uint32_t sb = smem_u32(smem);
    const int tid = threadIdx.x;
    const int warpId = tid >> 5;          // 0..3
    const int warpM  = warpId >> 1;       // 0..1 -> 64 m-rows
    const int warpN  = warpId & 1;        // 0..1 -> 64 n-cols
    const int n0 = blockIdx.x * BNT;
    const int m0 = blockIdx.y * BMT;
    const int ks = blockIdx.z;            // K-split 0/1
    const int kbase = ks * (K_DIM / 2);

    if (tid < 114) {   // codebook (227 rows, 2 per thread)
        *(uint4*)(smem + SM_CB + tid * 32) = *(const uint4*)(g_gp + tid * 16);
        if (tid * 2 + 1 < 227)
            *(uint4*)(smem + SM_CB + tid * 32 + 16) = *(const uint4*)(g_gp + tid * 16 + 8);
    }
    {   // sign LUT, 2 entries per thread
        #pragma unroll
        for (int u = 0; u < 2; u++) {
            uint32_t f = tid + u * 128;
            uint4 m;
            m.x = ((f & 1)  ? 0x8000u : 0u) | ((f & 2)   ? 0x80000000u : 0u);
            m.y = ((f & 4)  ? 0x8000u : 0u) | ((f & 8)   ? 0x80000000u : 0u);
            m.z = ((f & 16) ? 0x8000u : 0u) | ((f & 32)  ? 0x80000000u : 0u);
            m.w = ((f & 64) ? 0x8000u : 0u) | ((f & 128) ? 0x80000000u : 0u);
            *(uint4*)(smem + SM_LUT + f * 16) = m;
        }
    }
    __syncthreads();

    const int4* qrow = (const int4*)(Q + (size_t)(n0 + tid) * N_CODES) + ks * 128;

    wmma::fragment<wmma::accumulator, 16, 16, 16, float> acc[4][4];
    #pragma unroll
    for (int i = 0; i < 4; i++)
        #pragma unroll
        for (int j = 0; j < 4; j++)
            wmma::fill_fragment(acc[i][j], 0.0f);

    auto fill = [&](int c, int4 qa, int4 qb) {
        const int s = c & 1;
        const uint32_t abase = sb + SM_STAGE + s * STAGE_BYTES;
        #pragma unroll
        for (int u = 0; u < 8; u++) {
            int lin = tid + u * 128;
            int row = lin >> 3, c16 = lin & 7;
            cp_async16(abase + row * 144 + c16 * 16,
                       g_xh + (size_t)(m0 + row) * K_DIM + kbase + c * 64 + c16 * 8);
        }
        char* bb = smem + SM_STAGE + s * STAGE_BYTES + A_BYTES;
        const int qs[8] = {qa.x, qa.y, qa.z, qa.w, qb.x, qb.y, qb.z, qb.w};
        #pragma unroll
        for (int e = 0; e < 8; e++) {
            int idx = qs[e] + 32768;
            const uint4 cb = *(const uint4*)(smem + SM_CB  + (idx & 255) * 16);
            const uint4 sm = *(const uint4*)(smem + SM_LUT + (idx >> 8)  * 16);
            uint4 o;
            o.x = cb.x ^ sm.x;  o.y = cb.y ^ sm.y;
            o.z = cb.z ^ sm.z;  o.w = cb.w ^ sm.w;
            *(uint4*)(bb + tid * 144 + e * 16) = o;
        }
    };

    fill(0, qrow[0], qrow[1]);
    asm volatile("cp.async.commit_group;" ::: "memory");

    for (int i = 0; i < NCHUNK_S; i++) {
        if (i + 1 < NCHUNK_S)
            fill(i + 1, qrow[(i + 1) * 2], qrow[(i + 1) * 2 + 1]);
        asm volatile("cp.async.commit_group;" ::: "memory");
        asm volatile("cp.async.wait_group 1;" ::: "memory");
        __syncthreads();

        const int s = i & 1;
        const __half* As = (const __half*)(smem + SM_STAGE + s * STAGE_BYTES);
        const __half* Bs = (const __half*)(smem + SM_STAGE + s * STAGE_BYTES + A_BYTES);
        #pragma unroll
        for (int kk = 0; kk < 4; kk++) {
            wmma::fragment<wmma::matrix_a, 16, 16, 16, __half, wmma::row_major> a[4];
            wmma::fragment<wmma::matrix_b, 16, 16, 16, __half, wmma::col_major> b[4];
            #pragma unroll
            for (int ii = 0; ii < 4; ii++)
                wmma::load_matrix_sync(a[ii], &As[(warpM * 64 + ii * 16) * LDSM + kk * 16], LDSM);
            #pragma unroll
            for (int jj = 0; jj < 4; jj++)
                wmma::load_matrix_sync(b[jj], &Bs[(warpN * 64 + jj * 16) * LDSM + kk * 16], LDSM);
            #pragma unroll
            for (int ii = 0; ii < 4; ii++)
                #pragma unroll
                for (int jj = 0; jj < 4; jj++)
                    wmma::mma_sync(acc[ii][jj], a[ii], b[jj], acc[ii][jj]);
        }
        __syncthreads();
    }

    float* zbase = ks ? g_z2 : g_z;
    #pragma unroll
    for (int ii = 0; ii < 4; ii++)
        #pragma unroll
        for (int jj = 0; jj < 4; jj++)
            wmma::store_matrix_sync(
                &zbase[(size_t)(m0 + warpM * 64 + ii * 16) * M_DIM +
                       n0 + warpN * 64 + jj * 16],
                acc[ii][jj], M_DIM, wmma::mem_row_major);
}

// ---------------------------------------------------------------------------
// K4: out = SV * fwht(z0 + z1) * (Wscale*1024/sqrt(8192))
// ---------------------------------------------------------------------------
__global__ void __launch_bounds__(256) fwht_out_kernel(const float* __restrict__ SV,
                                                       const float* __restrict__ Wscale,
                                                       float* __restrict__ out)
{
    __shared__ float sm[M_DIM];
    const int row = blockIdx.x;
    const int t = threadIdx.x;
    const float* z0 = g_z  + (size_t)row * M_DIM;
    const float* z1 = g_z2 + (size_t)row * M_DIM;
    float v[32];
    #pragma unroll
    for (int r = 0; r < 32; r++) {
        int i = r * 256 + t;
        v[r] = z0[i] + z1[i];
    }
    fwht8192_core(v, sm, t);
    const float c = Wscale[0] * 11.313708498984761f;  // 1024/sqrt(8192)
    float* o = out + (size_t)row * M_DIM;
    #pragma unroll
    for (int r = 0; r < 32; r++) {
        int i = r * 256 + t;
        o[i] = v[r] * c * SV[i];
    }
}

// ---------------------------------------------------------------------------
extern "C" void kernel_launch(void* const* d_in, const int* in_sizes, int n_in,
                              void* d_out, int out_size)
{
    const float* x  = nullptr;  const int*   Q  = nullptr;
    const float* SU = nullptr;  const float* SV = nullptr;
    const float* Ws = nullptr;  const void*  gp = nullptr;
    for (int i = 0; i < n_in; i++) {
        int s = in_sizes[i];
        if      (s == T_ROWS * K_DIM)   x  = (const float*)d_in[i];
        else if (s == M_DIM * N_CODES)  Q  = (const int*)d_in[i];
        else if (s == 1)                Ws = (const float*)d_in[i];
        else if (s == K_DIM) { if (!SU) SU = (const float*)d_in[i];
                               else     SV = (const float*)d_in[i]; }
        else                            gp = d_in[i];
    }
    float* out = (float*)d_out;

    static bool smem_set = false;
    if (!smem_set) {
        cudaFuncSetAttribute(gemm_fused_kernel,
                             cudaFuncAttributeMaxDynamicSharedMemorySize, SMEM_GEMM);
        smem_set = true;
    }

    prep_gp_kernel<<<8, 256>>>(gp);
    fwht_in_kernel<<<T_ROWS, 256>>>(x, SU);
    dim3 grid(M_DIM / BNT, T_ROWS / BMT, 2);
    gemm_fused_kernel<<<grid, 128, SMEM_GEMM>>>(Q);
    fwht_out_kernel<<<T_ROWS, 256>>>(SV, Ws, out);
}